// round 3
// baseline (speedup 1.0000x reference)
#include <cuda_runtime.h>
#include <cuda_fp16.h>
#include <cstdint>

#define DEV __device__ __forceinline__

// ---------------- problem constants ----------------
static constexpr int HID    = 128;
static constexpr int BATCH  = 128;
static constexpr int NROWS  = 128 * 4096;     // 524288
static constexpr int NTILES = NROWS / 128;    // 4096

// ---------------- SMEM layout (byte offsets) ----------------
static constexpr int OFF_SBAR = 0;                   // stage mbarrier (8B)
static constexpr int OFF_CS   = 64;                  // c bias, 256 f32
static constexpr int OFF_W3   = 1088;                // 64 f32
static constexpr int OFF_B2C  = 1344;                // 64 f32
static constexpr int OFF_B3   = 1600;                // 1 f32
static constexpr int OFF_A1   = 2048;                // 128x128 f16 swizzled (32KB)
static constexpr int OFF_B1   = OFF_A1 + 32768;      // 256n x 128k f16 swizzled (64KB)
static constexpr int OFF_B2   = OFF_B1 + 65536;      // 64n x 256k f16 swizzled (32KB)
static constexpr int OFF_STG  = OFF_B2 + 32768;      // fp32 stage 128x128 (64KB)
static constexpr int SMEM_BYTES = OFF_STG + 65536;   // 198656

// ---------------- helpers ----------------
DEV uint32_t s2u(const void* p) {
    uint32_t a;
    asm("{ .reg .u64 t; cvta.to.shared.u64 t, %1; cvt.u32.u64 %0, t; }" : "=r"(a) : "l"(p));
    return a;
}

DEV uint32_t pack2(float a, float b) {
    __half2 h = __floats2half2_rn(a, b);
    return *reinterpret_cast<uint32_t*>(&h);
}

DEV void mbar_init(uint32_t mbar, uint32_t cnt) {
    asm volatile("mbarrier.init.shared.b64 [%0], %1;" :: "r"(mbar), "r"(cnt) : "memory");
}
DEV void mbar_expect(uint32_t mbar, uint32_t bytes) {
    asm volatile("mbarrier.arrive.expect_tx.shared.b64 _, [%0], %1;" :: "r"(mbar), "r"(bytes) : "memory");
}
DEV void mbar_wait(uint32_t mbar, uint32_t parity) {
    asm volatile(
        "{\n\t.reg .pred P;\n\t"
        "LW%=:\n\t"
        "mbarrier.try_wait.parity.acquire.cta.shared::cta.b64 P, [%0], %1, 0x989680;\n\t"
        "@P bra LD%=;\n\t"
        "bra LW%=;\n\t"
        "LD%=:\n\t}"
        :: "r"(mbar), "r"(parity) : "memory");
}
DEV void bulk_g2s(uint32_t dst, const void* src, uint32_t bytes, uint32_t mbar) {
    asm volatile(
        "cp.async.bulk.shared::cta.global.mbarrier::complete_tx::bytes [%0], [%1], %2, [%3];"
        :: "r"(dst), "l"(src), "r"(bytes), "r"(mbar) : "memory");
}

DEV void ldsm4(uint32_t* r, uint32_t addr) {
    asm volatile("ldmatrix.sync.aligned.m8n8.x4.shared.b16 {%0,%1,%2,%3}, [%4];"
        : "=r"(r[0]), "=r"(r[1]), "=r"(r[2]), "=r"(r[3]) : "r"(addr));
}

DEV void mma16816(float* c, const uint32_t* a, uint32_t b0, uint32_t b1) {
    asm volatile(
        "mma.sync.aligned.m16n8k16.row.col.f32.f16.f16.f32 "
        "{%0,%1,%2,%3}, {%4,%5,%6,%7}, {%8,%9}, {%0,%1,%2,%3};"
        : "+f"(c[0]), "+f"(c[1]), "+f"(c[2]), "+f"(c[3])
        : "r"(a[0]), "r"(a[1]), "r"(a[2]), "r"(a[3]), "r"(b0), "r"(b1));
}

// ---------------- per-batch bias: c[b] = b1 + new_nodes[b] @ W1[128:256] ----------------
__device__ float g_cbias[BATCH * 256];

__global__ void cbias_kernel(const float* __restrict__ new_nodes,
                             const float* __restrict__ W1,
                             const float* __restrict__ b1) {
    int b = blockIdx.x;
    int n = threadIdx.x;
    float acc = b1[n];
    const float* nb = new_nodes + (size_t)b * HID;
#pragma unroll 8
    for (int f = 0; f < HID; ++f)
        acc = fmaf(nb[f], W1[(size_t)(HID + f) * 256 + n], acc);
    g_cbias[b * 256 + n] = acc;
}

// ---------------- main fused kernel ----------------
__global__ void __launch_bounds__(256, 1)
edge_mlp_kernel(const float* __restrict__ nodes,   // [NROWS,128]
                const float* __restrict__ W1,      // [256,256]
                const float* __restrict__ W2,      // [256,64]
                const float* __restrict__ W3,      // [64]
                const float* __restrict__ b2,      // [64]
                const float* __restrict__ b3,      // [1]
                float* __restrict__ out)           // [NROWS]
{
    extern __shared__ char smem[];
    const uint32_t sb = s2u(smem);
    const int tid  = threadIdx.x;
    const int wid  = tid >> 5;
    const int lane = tid & 31;
    const int l7   = lane & 7;
    const int l3   = lane & 3;
    const int rsel = (lane >> 3) & 1;   // row-half selector for ldmatrix
    const int usub = lane >> 4;         // k-unit selector for ldmatrix

    float* c_s  = reinterpret_cast<float*>(smem + OFF_CS);
    float* w3_s = reinterpret_cast<float*>(smem + OFF_W3);
    float* b2_s = reinterpret_cast<float*>(smem + OFF_B2C);
    float* b3_s = reinterpret_cast<float*>(smem + OFF_B3);
    float* stg  = reinterpret_cast<float*>(smem + OFF_STG);

    const uint32_t sbar = sb + OFF_SBAR;

    if (tid == 0) mbar_init(sbar, 1);
    __syncthreads();

    // kick off first tile load ASAP (overlaps weight conversion)
    if (tid == 0) {
        mbar_expect(sbar, 65536);
        bulk_g2s(sb + OFF_STG, nodes + (size_t)blockIdx.x * (128 * HID), 65536, sbar);
    }

    // small constants
    if (tid < 64) { w3_s[tid] = W3[tid]; b2_s[tid] = b2[tid]; }
    if (tid == 0) b3_s[0] = b3[0];

    // B1: [n=256][k=128] f16, 256B rows, XOR swizzle (unit16B ^ row&7). B1[n][k]=W1[k*256+n]
    {
        const int n = tid;
#pragma unroll 4
        for (int kp = 0; kp < 64; ++kp) {
            float a = W1[(size_t)(2 * kp) * 256 + n];
            float b = W1[(size_t)(2 * kp + 1) * 256 + n];
            uint32_t addr = (uint32_t)(n * 256 + ((((kp >> 2) ^ (n & 7)) << 4)) + (kp & 3) * 4);
            *reinterpret_cast<uint32_t*>(smem + OFF_B1 + addr) = pack2(a, b);
        }
    }
    // B2: [n=64][k=256] f16, 512B rows, same swizzle. B2[n][k]=W2[k*64+n]
    {
#pragma unroll 4
        for (int j = 0; j < 32; ++j) {
            int idx = tid + j * 256;
            int n  = idx & 63;
            int kp = idx >> 6;              // 0..127
            float a = W2[(size_t)(2 * kp) * 64 + n];
            float b = W2[(size_t)(2 * kp + 1) * 64 + n];
            uint32_t addr = (uint32_t)(n * 512 + (((kp >> 2) ^ (n & 7)) << 4) + (kp & 3) * 4);
            *reinterpret_cast<uint32_t*>(smem + OFF_B2 + addr) = pack2(a, b);
        }
    }
    __syncthreads();

    // per-warp ldmatrix lane bases
    const int aRow = wid * 16 + l7 + (rsel << 3);           // A1 row this lane addresses
    const uint32_t aBase = sb + OFF_A1 + (uint32_t)aRow * 256;
    const uint32_t b1LaneBase = sb + OFF_B1 + (uint32_t)((l7 + (rsel << 3)) * 256);
    const uint32_t b2LaneBase = sb + OFF_B2 + (uint32_t)((l7 + (rsel << 3)) * 512);

    int i = 0;
    for (int t = blockIdx.x; t < NTILES; t += gridDim.x, ++i) {
        const int b = t >> 5;
        c_s[tid] = g_cbias[b * 256 + tid];          // safe: loop-end barrier

        // wait staged input
        mbar_wait(sbar, (uint32_t)(i & 1));

        // convert fp32 -> f16 swizzled A1
#pragma unroll 4
        for (int j = 0; j < 32; ++j) {
            int idx = tid + j * 256;
            int m  = idx >> 6;                       // row 0..127
            int kp = idx & 63;                       // f16x2 index in row
            float2 v = *reinterpret_cast<const float2*>(stg + (size_t)m * HID + 2 * kp);
            uint32_t addr = (uint32_t)(m * 256 + (((kp >> 2) ^ (m & 7)) << 4) + (kp & 3) * 4);
            *reinterpret_cast<uint32_t*>(smem + OFF_A1 + addr) = pack2(v.x, v.y);
        }
        __syncthreads();

        // prefetch next tile (stage fully consumed)
        const int tn = t + gridDim.x;
        if (tid == 0 && tn < NTILES) {
            mbar_expect(sbar, 65536);
            bulk_g2s(sb + OFF_STG, nodes + (size_t)tn * (128 * HID), 65536, sbar);
        }

        // load A fragments: 16 rows x 128 k -> 8 k-steps
        uint32_t aregs[8][4];
#pragma unroll
        for (int s = 0; s < 8; ++s)
            ldsm4(aregs[s], aBase + (uint32_t)((((s << 1) + usub) ^ l7) << 4));

        float c2[8][4];
#pragma unroll
        for (int f = 0; f < 8; ++f)
#pragma unroll
            for (int q = 0; q < 4; ++q) c2[f][q] = 0.f;

        // 4 chunks of 64 layer-1 output cols; layer2 fused per chunk
#pragma unroll
        for (int ch = 0; ch < 4; ++ch) {
            const int NB = ch * 64;

            float c1[8][4];
#pragma unroll
            for (int f = 0; f < 8; ++f)
#pragma unroll
                for (int q = 0; q < 4; ++q) c1[f][q] = 0.f;

            // layer 1: C1[16 x 64] += A[16 x 128] * B1[cols NB..NB+63]
#pragma unroll
            for (int p = 0; p < 4; ++p) {
                const uint32_t bBase = b1LaneBase + (uint32_t)((NB + p * 16) * 256);
#pragma unroll
                for (int s = 0; s < 8; ++s) {
                    uint32_t br[4];
                    ldsm4(br, bBase + (uint32_t)((((s << 1) + usub) ^ l7) << 4));
                    mma16816(c1[2 * p],     aregs[s], br[0], br[2]);
                    mma16816(c1[2 * p + 1], aregs[s], br[1], br[3]);
                }
            }

            // epilogue 1 in registers: relu(+c) -> pack f16 -> layer-2 A frags
            uint32_t a2[4][4];
#pragma unroll
            for (int s = 0; s < 4; ++s) {
                const int f0 = 2 * s, f1 = 2 * s + 1;
                const int col0 = NB + f0 * 8 + l3 * 2;
                float2 cva = *reinterpret_cast<const float2*>(&c_s[col0]);
                float2 cvb = *reinterpret_cast<const float2*>(&c_s[col0 + 8]);
                a2[s][0] = pack2(fmaxf(c1[f0][0] + cva.x, 0.f), fmaxf(c1[f0][1] + cva.y, 0.f));
                a2[s][1] = pack2(fmaxf(c1[f0][2] + cva.x, 0.f), fmaxf(c1[f0][3] + cva.y, 0.f));
                a2[s][2] = pack2(fmaxf(c1[f1][0] + cvb.x, 0.f), fmaxf(c1[f1][1] + cvb.y, 0.f));
                a2[s][3] = pack2(fmaxf(c1[f1][2] + cvb.x, 0.f), fmaxf(c1[f1][3] + cvb.y, 0.f));
            }

            // layer 2 partial: C2[16 x 64] += H1chunk[16 x 64] * B2[k = NB..NB+63]
#pragma unroll
            for (int s = 0; s < 4; ++s) {
                const int ks = ch * 4 + s;
#pragma unroll
                for (int p2 = 0; p2 < 4; ++p2) {
                    uint32_t br[4];
                    ldsm4(br, b2LaneBase + (uint32_t)(p2 * 16 * 512) +
                              (uint32_t)((((ks << 1) + usub) ^ l7) << 4));
                    mma16816(c2[2 * p2],     a2[s], br[0], br[2]);
                    mma16816(c2[2 * p2 + 1], a2[s], br[1], br[3]);
                }
            }
        }

        // epilogue 2: relu(C2 + b2) . W3 + b3 -> sigmoid -> out
        {
            float accl = 0.f, acch = 0.f;
#pragma unroll
            for (int f2 = 0; f2 < 8; ++f2) {
                const int col = f2 * 8 + l3 * 2;
                float w0 = w3_s[col], w1 = w3_s[col + 1];
                float bb0 = b2_s[col], bb1 = b2_s[col + 1];
                accl = fmaf(fmaxf(c2[f2][0] + bb0, 0.f), w0, accl);
                accl = fmaf(fmaxf(c2[f2][1] + bb1, 0.f), w1, accl);
                acch = fmaf(fmaxf(c2[f2][2] + bb0, 0.f), w0, acch);
                acch = fmaf(fmaxf(c2[f2][3] + bb1, 0.f), w1, acch);
            }
            accl += __shfl_xor_sync(0xffffffffu, accl, 1);
            accl += __shfl_xor_sync(0xffffffffu, accl, 2);
            acch += __shfl_xor_sync(0xffffffffu, acch, 1);
            acch += __shfl_xor_sync(0xffffffffu, acch, 2);
            if (l3 == 0) {
                const int row = t * 128 + wid * 16 + (lane >> 2);
                const float bias3 = b3_s[0];
                out[row]     = 1.f / (1.f + __expf(-(accl + bias3)));
                out[row + 8] = 1.f / (1.f + __expf(-(acch + bias3)));
            }
        }

        __syncthreads();   // protect A1 / c_s for next iteration
    }
}

// ---------------- launch ----------------
extern "C" void kernel_launch(void* const* d_in, const int* in_sizes, int n_in,
                              void* d_out, int out_size) {
    const float* nodes = (const float*)d_in[0];   // [128,4096,128]
    const float* newn  = (const float*)d_in[1];   // [128,1,128]
    const float* W1    = (const float*)d_in[2];   // [256,256]
    const float* b1    = (const float*)d_in[3];   // [256]
    const float* W2    = (const float*)d_in[4];   // [256,64]
    const float* b2    = (const float*)d_in[5];   // [64]
    const float* W3    = (const float*)d_in[6];   // [64,1]
    const float* b3    = (const float*)d_in[7];   // [1]
    float* out = (float*)d_out;

    (void)in_sizes; (void)n_in; (void)out_size;

    cudaFuncSetAttribute(edge_mlp_kernel,
                         cudaFuncAttributeMaxDynamicSharedMemorySize, SMEM_BYTES);

    int nsm = 148;
    cudaDeviceGetAttribute(&nsm, cudaDevAttrMultiProcessorCount, 0);
    if (nsm <= 0) nsm = 148;
    if (nsm > NTILES) nsm = NTILES;

    cbias_kernel<<<BATCH, 256>>>(newn, W1, b1);
    edge_mlp_kernel<<<nsm, 256, SMEM_BYTES>>>(nodes, W1, W2, W3, b2, b3, out);
}

// round 4
// speedup vs baseline: 1.1659x; 1.1659x over previous
#include <cuda_runtime.h>
#include <cuda_fp16.h>
#include <cstdint>

#define DEV __device__ __forceinline__

// ---------------- problem constants ----------------
static constexpr int HID    = 128;
static constexpr int BATCH  = 128;
static constexpr int NROWS  = 128 * 4096;     // 524288
static constexpr int NT2    = NROWS / 256;    // 2048 tiles of 256 rows

// ---------------- SMEM layout (byte offsets) ----------------
static constexpr int OFF_BAR  = 0;                  // mbarrier (8B)
static constexpr int OFF_W3   = 64;                 // 64 f32
static constexpr int OFF_B2C  = 320;                // 64 f32
static constexpr int OFF_B3   = 576;                // 1 f32
static constexpr int OFF_CS   = 1024;               // [2][256] f32 (2KB)
static constexpr int OFF_A1   = 3072;               // 256 x 128 f16 swizzled (64KB)
static constexpr int OFF_B1   = OFF_A1 + 65536;     // 256n x 128k f16 swizzled (64KB)
static constexpr int OFF_B2   = OFF_B1 + 65536;     // 64n x 256k f16 swizzled (32KB)
static constexpr int OFF_STG  = OFF_B2 + 32768;     // fp32 stage: 128 rows x 128 (64KB)
static constexpr int SMEM_BYTES = OFF_STG + 65536;  // 232448 == opt-in max

// ---------------- helpers ----------------
DEV uint32_t s2u(const void* p) {
    uint32_t a;
    asm("{ .reg .u64 t; cvta.to.shared.u64 t, %1; cvt.u32.u64 %0, t; }" : "=r"(a) : "l"(p));
    return a;
}
DEV uint32_t pack2(float a, float b) {
    __half2 h = __floats2half2_rn(a, b);
    return *reinterpret_cast<uint32_t*>(&h);
}
DEV void mbar_init(uint32_t mbar, uint32_t cnt) {
    asm volatile("mbarrier.init.shared.b64 [%0], %1;" :: "r"(mbar), "r"(cnt) : "memory");
}
DEV void mbar_expect(uint32_t mbar, uint32_t bytes) {
    asm volatile("mbarrier.arrive.expect_tx.shared.b64 _, [%0], %1;" :: "r"(mbar), "r"(bytes) : "memory");
}
DEV void mbar_wait(uint32_t mbar, uint32_t parity) {
    asm volatile(
        "{\n\t.reg .pred P;\n\t"
        "LW%=:\n\t"
        "mbarrier.try_wait.parity.acquire.cta.shared::cta.b64 P, [%0], %1, 0x989680;\n\t"
        "@P bra LD%=;\n\t"
        "bra LW%=;\n\t"
        "LD%=:\n\t}"
        :: "r"(mbar), "r"(parity) : "memory");
}
DEV void bulk_g2s(uint32_t dst, const void* src, uint32_t bytes, uint32_t mbar) {
    asm volatile(
        "cp.async.bulk.shared::cta.global.mbarrier::complete_tx::bytes [%0], [%1], %2, [%3];"
        :: "r"(dst), "l"(src), "r"(bytes), "r"(mbar) : "memory");
}
DEV void ldsm4(uint32_t* r, uint32_t addr) {
    asm volatile("ldmatrix.sync.aligned.m8n8.x4.shared.b16 {%0,%1,%2,%3}, [%4];"
        : "=r"(r[0]), "=r"(r[1]), "=r"(r[2]), "=r"(r[3]) : "r"(addr));
}
DEV void mma16816(float* c, const uint32_t* a, uint32_t b0, uint32_t b1) {
    asm volatile(
        "mma.sync.aligned.m16n8k16.row.col.f32.f16.f16.f32 "
        "{%0,%1,%2,%3}, {%4,%5,%6,%7}, {%8,%9}, {%0,%1,%2,%3};"
        : "+f"(c[0]), "+f"(c[1]), "+f"(c[2]), "+f"(c[3])
        : "r"(a[0]), "r"(a[1]), "r"(a[2]), "r"(a[3]), "r"(b0), "r"(b1));
}
DEV void named_bar(int id) {
    asm volatile("bar.sync %0, 128;" :: "r"(id) : "memory");
}

// ---------------- per-batch bias: c[b] = b1 + new_nodes[b] @ W1[128:256] ----------------
__device__ float g_cbias[BATCH * 256];

__global__ void cbias_kernel(const float* __restrict__ new_nodes,
                             const float* __restrict__ W1,
                             const float* __restrict__ b1) {
    int b = blockIdx.x;
    int n = threadIdx.x;
    float acc = b1[n];
    const float* nb = new_nodes + (size_t)b * HID;
#pragma unroll 8
    for (int f = 0; f < HID; ++f)
        acc = fmaf(nb[f], W1[(size_t)(HID + f) * 256 + n], acc);
    g_cbias[b * 256 + n] = acc;
}

// ---------------- main fused kernel ----------------
__global__ void __launch_bounds__(256, 1)
edge_mlp_kernel(const float* __restrict__ nodes,   // [NROWS,128]
                const float* __restrict__ W1,      // [256,256]
                const float* __restrict__ W2,      // [256,64]
                const float* __restrict__ W3,      // [64]
                const float* __restrict__ b2,      // [64]
                const float* __restrict__ b3,      // [1]
                float* __restrict__ out)           // [NROWS]
{
    extern __shared__ char smem[];
    const uint32_t sb = s2u(smem);
    const int tid  = threadIdx.x;
    const int wid  = tid >> 5;
    const int lane = tid & 31;
    const int l7   = lane & 7;
    const int l3   = lane & 3;
    const int rsel = (lane >> 3) & 1;   // row-half selector for ldmatrix
    const int usub = lane >> 4;         // k-unit selector for ldmatrix
    const int g    = tid >> 7;          // group 0: warps 0-3 (rows 0-127); group 1: warps 4-7
    const int gtid = tid & 127;

    float* w3_s = reinterpret_cast<float*>(smem + OFF_W3);
    float* b2_s = reinterpret_cast<float*>(smem + OFF_B2C);
    float* b3_s = reinterpret_cast<float*>(smem + OFF_B3);
    float* cs_g = reinterpret_cast<float*>(smem + OFF_CS) + g * 256;
    float* stg  = reinterpret_cast<float*>(smem + OFF_STG);

    const uint32_t sbar = sb + OFF_BAR;

    if (tid == 0) mbar_init(sbar, 1);
    __syncthreads();

    // load 0: tile blockIdx.x, rows [0,128) — issued ASAP, overlaps weight conversion
    if (tid == 0) {
        mbar_expect(sbar, 65536);
        bulk_g2s(sb + OFF_STG, nodes + (size_t)blockIdx.x * (256 * HID), 65536, sbar);
    }

    // small constants
    if (tid < 64) { w3_s[tid] = W3[tid]; b2_s[tid] = b2[tid]; }
    if (tid == 0) b3_s[0] = b3[0];

    // B1: [n=256][k=128] f16, 256B rows, XOR swizzle (unit16B ^ row&7). B1[n][k]=W1[k*256+n]
    {
        const int n = tid;
#pragma unroll 4
        for (int kp = 0; kp < 64; ++kp) {
            float a = W1[(size_t)(2 * kp) * 256 + n];
            float b = W1[(size_t)(2 * kp + 1) * 256 + n];
            uint32_t addr = (uint32_t)(n * 256 + (((kp >> 2) ^ (n & 7)) << 4) + (kp & 3) * 4);
            *reinterpret_cast<uint32_t*>(smem + OFF_B1 + addr) = pack2(a, b);
        }
    }
    // B2: [n=64][k=256] f16, 512B rows, same swizzle. B2[n][k]=W2[k*64+n]
    {
#pragma unroll 4
        for (int j = 0; j < 32; ++j) {
            int idx = tid + j * 256;
            int n  = idx & 63;
            int kp = idx >> 6;              // 0..127
            float a = W2[(size_t)(2 * kp) * 64 + n];
            float b = W2[(size_t)(2 * kp + 1) * 64 + n];
            uint32_t addr = (uint32_t)(n * 512 + (((kp >> 2) ^ (n & 7)) << 4) + (kp & 3) * 4);
            *reinterpret_cast<uint32_t*>(smem + OFF_B2 + addr) = pack2(a, b);
        }
    }
    __syncthreads();
    // after this point: NO full-CTA barriers; the two groups run decoupled.

    // per-warp ldmatrix lane bases
    const uint32_t aBase0 = sb + OFF_A1 + (uint32_t)((wid * 32      + l7 + (rsel << 3)) * 256);
    const uint32_t aBase1 = sb + OFF_A1 + (uint32_t)((wid * 32 + 16 + l7 + (rsel << 3)) * 256);
    const uint32_t b1LaneBase = sb + OFF_B1 + (uint32_t)((l7 + (rsel << 3)) * 256);
    const uint32_t b2LaneBase = sb + OFF_B2 + (uint32_t)((l7 + (rsel << 3)) * 512);

    const int grid = gridDim.x;

    for (int t = blockIdx.x; t < NT2; t += grid) {
        // ---- wait my group's staged half (parity == g by construction) ----
        mbar_wait(sbar, (uint32_t)g);

        // per-tile bias into group-private copy (batch constant across the tile)
        const int b = t >> 4;
        cs_g[gtid]       = g_cbias[b * 256 + gtid];
        cs_g[gtid + 128] = g_cbias[b * 256 + 128 + gtid];

        // ---- convert stage fp32 -> f16 swizzled A1 rows [g*128, g*128+128) ----
#pragma unroll 4
        for (int j = 0; j < 64; ++j) {
            int idx = gtid + j * 128;
            int m  = idx >> 6;                       // local row 0..127
            int kp = idx & 63;                       // f16x2 index in row
            float2 v = reinterpret_cast<const float2*>(stg)[m * 64 + kp];
            uint32_t addr = (uint32_t)((g * 128 + m) * 256 + (((kp >> 2) ^ (m & 7)) << 4) + (kp & 3) * 4);
            *reinterpret_cast<uint32_t*>(smem + OFF_A1 + addr) = pack2(v.x, v.y);
        }
        named_bar(1 + g);

        // ---- group leader issues the NEXT load (stage buffer now free) ----
        // g==0 just consumed load 2k   -> issue load 2k+1: tile t, rows [128,256)
        // g==1 just consumed load 2k+1 -> issue load 2k+2: tile t+grid, rows [0,128)
        if (gtid == 0) {
            if (g == 0) {
                mbar_expect(sbar, 65536);
                bulk_g2s(sb + OFF_STG, nodes + ((size_t)t * 256 + 128) * HID, 65536, sbar);
            } else if (t + grid < NT2) {
                mbar_expect(sbar, 65536);
                bulk_g2s(sb + OFF_STG, nodes + (size_t)(t + grid) * 256 * HID, 65536, sbar);
            }
        }

        // ---- load A fragments: 32 rows x 128 k -> 2 halves x 8 k-steps ----
        uint32_t areg[2][8][4];
#pragma unroll
        for (int s = 0; s < 8; ++s) {
            ldsm4(areg[0][s], aBase0 + (uint32_t)((((s << 1) + usub) ^ l7) << 4));
            ldsm4(areg[1][s], aBase1 + (uint32_t)((((s << 1) + usub) ^ l7) << 4));
        }

        float c2[2][8][4];
#pragma unroll
        for (int h = 0; h < 2; ++h)
#pragma unroll
            for (int f = 0; f < 8; ++f)
#pragma unroll
                for (int q = 0; q < 4; ++q) c2[h][f][q] = 0.f;

        // ---- fused layers 1+2, p = 16-col block of layer-1 output ----
        for (int p = 0; p < 16; ++p) {
            float c1[2][2][4];
#pragma unroll
            for (int h = 0; h < 2; ++h)
#pragma unroll
                for (int n = 0; n < 2; ++n)
#pragma unroll
                    for (int q = 0; q < 4; ++q) c1[h][n][q] = 0.f;

            const uint32_t bB = b1LaneBase + (uint32_t)(p * 16 * 256);
#pragma unroll
            for (int s = 0; s < 8; ++s) {
                uint32_t br[4];
                ldsm4(br, bB + (uint32_t)((((s << 1) + usub) ^ l7) << 4));
                mma16816(c1[0][0], areg[0][s], br[0], br[2]);
                mma16816(c1[0][1], areg[0][s], br[1], br[3]);
                mma16816(c1[1][0], areg[1][s], br[0], br[2]);
                mma16816(c1[1][1], areg[1][s], br[1], br[3]);
            }

            // epilogue-1 in registers: relu(+c) -> pack f16 -> layer-2 A frags
            float2 cva = *reinterpret_cast<const float2*>(&cs_g[p * 16 + l3 * 2]);
            float2 cvb = *reinterpret_cast<const float2*>(&cs_g[p * 16 + 8 + l3 * 2]);
            uint32_t a2[2][4];
#pragma unroll
            for (int h = 0; h < 2; ++h) {
                a2[h][0] = pack2(fmaxf(c1[h][0][0] + cva.x, 0.f), fmaxf(c1[h][0][1] + cva.y, 0.f));
                a2[h][1] = pack2(fmaxf(c1[h][0][2] + cva.x, 0.f), fmaxf(c1[h][0][3] + cva.y, 0.f));
                a2[h][2] = pack2(fmaxf(c1[h][1][0] + cvb.x, 0.f), fmaxf(c1[h][1][1] + cvb.y, 0.f));
                a2[h][3] = pack2(fmaxf(c1[h][1][2] + cvb.x, 0.f), fmaxf(c1[h][1][3] + cvb.y, 0.f));
            }

            // layer-2 partial: k-step p
            const uint32_t koff = (uint32_t)((((p << 1) + usub) ^ l7) << 4);
#pragma unroll
            for (int p2 = 0; p2 < 4; ++p2) {
                uint32_t br2[4];
                ldsm4(br2, b2LaneBase + (uint32_t)(p2 * 16 * 512) + koff);
                mma16816(c2[0][2 * p2],     a2[0], br2[0], br2[2]);
                mma16816(c2[0][2 * p2 + 1], a2[0], br2[1], br2[3]);
                mma16816(c2[1][2 * p2],     a2[1], br2[0], br2[2]);
                mma16816(c2[1][2 * p2 + 1], a2[1], br2[1], br2[3]);
            }
        }

        // ---- epilogue 2: relu(C2 + b2) . W3 + b3 -> sigmoid -> out ----
        const float bias3 = b3_s[0];
#pragma unroll
        for (int h = 0; h < 2; ++h) {
            float accl = 0.f, acch = 0.f;
#pragma unroll
            for (int f2 = 0; f2 < 8; ++f2) {
                const int col = f2 * 8 + l3 * 2;
                float w0 = w3_s[col], w1 = w3_s[col + 1];
                float bb0 = b2_s[col], bb1 = b2_s[col + 1];
                accl = fmaf(fmaxf(c2[h][f2][0] + bb0, 0.f), w0, accl);
                accl = fmaf(fmaxf(c2[h][f2][1] + bb1, 0.f), w1, accl);
                acch = fmaf(fmaxf(c2[h][f2][2] + bb0, 0.f), w0, acch);
                acch = fmaf(fmaxf(c2[h][f2][3] + bb1, 0.f), w1, acch);
            }
            accl += __shfl_xor_sync(0xffffffffu, accl, 1);
            accl += __shfl_xor_sync(0xffffffffu, accl, 2);
            acch += __shfl_xor_sync(0xffffffffu, acch, 1);
            acch += __shfl_xor_sync(0xffffffffu, acch, 2);
            if (l3 == 0) {
                const int row = t * 256 + wid * 32 + 16 * h + (lane >> 2);
                out[row]     = 1.f / (1.f + __expf(-(accl + bias3)));
                out[row + 8] = 1.f / (1.f + __expf(-(acch + bias3)));
            }
        }

        named_bar(1 + g);   // protect cs_g (and ordering) for the next iteration
    }
}

// ---------------- launch ----------------
extern "C" void kernel_launch(void* const* d_in, const int* in_sizes, int n_in,
                              void* d_out, int out_size) {
    const float* nodes = (const float*)d_in[0];   // [128,4096,128]
    const float* newn  = (const float*)d_in[1];   // [128,1,128]
    const float* W1    = (const float*)d_in[2];   // [256,256]
    const float* b1    = (const float*)d_in[3];   // [256]
    const float* W2    = (const float*)d_in[4];   // [256,64]
    const float* b2    = (const float*)d_in[5];   // [64]
    const float* W3    = (const float*)d_in[6];   // [64,1]
    const float* b3    = (const float*)d_in[7];   // [1]
    float* out = (float*)d_out;

    (void)in_sizes; (void)n_in; (void)out_size;

    cudaFuncSetAttribute(edge_mlp_kernel,
                         cudaFuncAttributeMaxDynamicSharedMemorySize, SMEM_BYTES);

    int nsm = 148;
    cudaDeviceGetAttribute(&nsm, cudaDevAttrMultiProcessorCount, 0);
    if (nsm <= 0) nsm = 148;
    if (nsm > NT2) nsm = NT2;

    cbias_kernel<<<BATCH, 256>>>(newn, W1, b1);
    edge_mlp_kernel<<<nsm, 256, SMEM_BYTES>>>(nodes, W1, W2, W3, b2, b3, out);
}